// round 3
// baseline (speedup 1.0000x reference)
#include <cuda_runtime.h>
#include <math.h>

#define N_NODES 100000
#define E_EDGES 400000
#define IN_DIM  100
#define D       200
#define D3      600
#define NUM_STEPS 4

// ---------------- scratch (static device globals; 16B-aligned for float4) ----
__device__ __align__(16) float g_h   [(size_t)N_NODES * D];
__device__ __align__(16) float g_m   [(size_t)N_NODES * D];
__device__ __align__(16) float g_aggr[(size_t)N_NODES * D];
__device__ __align__(16) float g_gi  [(size_t)N_NODES * D3];
__device__ __align__(16) float g_gh  [(size_t)N_NODES * D3];
__device__ __align__(16) float g_Bih [D * D3];
__device__ __align__(16) float g_Bhh [D * D3];
__device__ __align__(16) float g_pool[D];
__device__ int g_src[E_EDGES];
__device__ int g_dst[E_EDGES];
__device__ int g_ei_is64;   // 1 if edge_index stored as int64, 0 if int32

// ---------------- edge-index dtype detection + conversion --------------------
// If the 800k-element buffer is int64, every high 32-bit word of the first
// entries is 0 (indices < 1e5). If it's int32, those words are real indices
// (random in [0,1e5), essentially never all zero over 4096 samples).
__global__ void detect_ei_kernel(const unsigned int* __restrict__ w) {
    if (threadIdx.x == 0) {
        int is64 = 1;
        for (int i = 0; i < 4096; i++)
            if (w[2 * i + 1] != 0u) { is64 = 0; break; }
        g_ei_is64 = is64;
    }
}

__global__ void convert_ei_kernel(const void* __restrict__ ei) {
    int e = blockIdx.x * blockDim.x + threadIdx.x;
    if (e >= E_EDGES) return;
    int s, d;
    if (g_ei_is64) {
        const long long* p = (const long long*)ei;
        s = (int)p[e];
        d = (int)p[E_EDGES + e];
    } else {
        const int* p = (const int*)ei;
        s = p[e];
        d = p[E_EDGES + e];
    }
    // defensive clamp: a wrong dtype guess becomes rel_err, not an IMA
    s = min(max(s, 0), N_NODES - 1);
    d = min(max(d, 0), N_NODES - 1);
    g_src[e] = s;
    g_dst[e] = d;
}

// ---------------- helpers ----------------------------------------------------
__global__ void zero4_kernel(float* __restrict__ p, int n4) {
    int i = blockIdx.x * blockDim.x + threadIdx.x;
    if (i < n4) ((float4*)p)[i] = make_float4(0.f, 0.f, 0.f, 0.f);
}

__global__ void init_h_kernel(const float* __restrict__ x) {
    int idx = blockIdx.x * blockDim.x + threadIdx.x;
    if (idx >= N_NODES * D) return;
    int n = idx / D, d = idx - n * D;
    g_h[idx] = (d < IN_DIM) ? x[n * IN_DIM + d] : 0.f;
}

// w: [D3, D] row-major  ->  o: [D, D3] row-major  (o = w^T)
__global__ void transpose_kernel(const float* __restrict__ w, float* __restrict__ o) {
    int idx = blockIdx.x * blockDim.x + threadIdx.x;
    if (idx >= D3 * D) return;
    int r = idx / D, c = idx - r * D;
    o[c * D3 + r] = w[idx];
}

// ---------------- SGEMM: C[M,Nc] = A[M,K] @ B[K,Nc] --------------------------
// BM=BN=128, BK=8, 256 threads, 8x8 microtile in 4+4 split halves.
__global__ __launch_bounds__(256) void sgemm128(
    const float* __restrict__ A, const float* __restrict__ B, float* __restrict__ C,
    int M, int Nc, int K)
{
    __shared__ float As[8][128];
    __shared__ float Bs[8][128];
    const int tid = threadIdx.x;
    const int tx = tid & 15;
    const int ty = tid >> 4;
    const int rowBase = blockIdx.y * 128;
    const int colBase = blockIdx.x * 128;

    float acc[8][8];
#pragma unroll
    for (int i = 0; i < 8; i++)
#pragma unroll
        for (int j = 0; j < 8; j++) acc[i][j] = 0.f;

    const int aRow = tid >> 1;       // 0..127
    const int aCol = (tid & 1) * 4;  // 0 or 4
    const int bRow = tid >> 5;       // 0..7
    const int bCol = (tid & 31) * 4; // 0..124

    for (int k0 = 0; k0 < K; k0 += 8) {
        // A tile 128x8 (transposed into SMEM); row stride K=200 floats keeps
        // 16B alignment of (ar*K + k0 + aCol).
        float4 av = make_float4(0.f, 0.f, 0.f, 0.f);
        int ar = rowBase + aRow;
        if (ar < M) av = *(const float4*)(A + (size_t)ar * K + k0 + aCol);
        As[aCol + 0][aRow] = av.x;
        As[aCol + 1][aRow] = av.y;
        As[aCol + 2][aRow] = av.z;
        As[aCol + 3][aRow] = av.w;

        // B tile 8x128
        float4 bv = make_float4(0.f, 0.f, 0.f, 0.f);
        int bc = colBase + bCol;
        const float* Brow = B + (size_t)(k0 + bRow) * Nc;
        if (bc + 3 < Nc) {
            bv = *(const float4*)(Brow + bc);
        } else {
            if (bc + 0 < Nc) bv.x = Brow[bc + 0];
            if (bc + 1 < Nc) bv.y = Brow[bc + 1];
            if (bc + 2 < Nc) bv.z = Brow[bc + 2];
        }
        *(float4*)&Bs[bRow][bCol] = bv;
        __syncthreads();

#pragma unroll
        for (int kk = 0; kk < 8; kk++) {
            float a[8], b[8];
            *(float4*)&a[0] = *(const float4*)&As[kk][ty * 4];
            *(float4*)&a[4] = *(const float4*)&As[kk][64 + ty * 4];
            *(float4*)&b[0] = *(const float4*)&Bs[kk][tx * 4];
            *(float4*)&b[4] = *(const float4*)&Bs[kk][64 + tx * 4];
#pragma unroll
            for (int i = 0; i < 8; i++)
#pragma unroll
                for (int j = 0; j < 8; j++) acc[i][j] = fmaf(a[i], b[j], acc[i][j]);
        }
        __syncthreads();
    }

#pragma unroll
    for (int i = 0; i < 8; i++) {
        int r = rowBase + ((i < 4) ? (ty * 4 + i) : (64 + ty * 4 + (i - 4)));
        if (r >= M) continue;
        float* Crow = C + (size_t)r * Nc;
#pragma unroll
        for (int half = 0; half < 2; half++) {
            int c = colBase + half * 64 + tx * 4;
            float4 v;
            v.x = acc[i][half * 4 + 0];
            v.y = acc[i][half * 4 + 1];
            v.z = acc[i][half * 4 + 2];
            v.w = acc[i][half * 4 + 3];
            if (c + 3 < Nc) {
                *(float4*)(Crow + c) = v;
            } else {
                if (c + 0 < Nc) Crow[c + 0] = v.x;
                if (c + 1 < Nc) Crow[c + 1] = v.y;
                if (c + 2 < Nc) Crow[c + 2] = v.z;
            }
        }
    }
}

// ---------------- edge scatter-add: aggr[dst] += m[src] ----------------------
// 50 threads per edge, each does one float4 slice -> 4 atomics.
__global__ void scatter_add_kernel() {
    int idx = blockIdx.x * blockDim.x + threadIdx.x;
    if (idx >= E_EDGES * 50) return;
    int e = idx / 50;
    int c = (idx - e * 50) * 4;
    int s = g_src[e];
    int d = g_dst[e];
    float4 v = *(const float4*)(g_m + (size_t)s * D + c);
    float* out = g_aggr + (size_t)d * D + c;
    atomicAdd(out + 0, v.x);
    atomicAdd(out + 1, v.y);
    atomicAdd(out + 2, v.z);
    atomicAdd(out + 3, v.w);
}

// ---------------- GRU elementwise --------------------------------------------
__device__ __forceinline__ float gru1(float ir, float iz, float inn,
                                      float hr, float hz, float hn, float h) {
    float r = 1.f / (1.f + expf(-(ir + hr)));
    float z = 1.f / (1.f + expf(-(iz + hz)));
    float n = tanhf(inn + r * hn);
    return (1.f - z) * n + z * h;
}

__global__ void gru_kernel(const float* __restrict__ b_ih, const float* __restrict__ b_hh) {
    int idx = blockIdx.x * blockDim.x + threadIdx.x;
    if (idx >= N_NODES * 50) return;
    int n = idx / 50;
    int c = (idx - n * 50) * 4;
    size_t gbase = (size_t)n * D3;
    float4 ir  = *(const float4*)(g_gi + gbase + c);
    float4 iz  = *(const float4*)(g_gi + gbase + D + c);
    float4 inn = *(const float4*)(g_gi + gbase + 2 * D + c);
    float4 hr  = *(const float4*)(g_gh + gbase + c);
    float4 hz  = *(const float4*)(g_gh + gbase + D + c);
    float4 hn  = *(const float4*)(g_gh + gbase + 2 * D + c);
    // biases: scalar loads (base alignment of b_ih+200 etc. not guaranteed 16B)
    float bir0 = b_ih[c],         bir1 = b_ih[c + 1],         bir2 = b_ih[c + 2],         bir3 = b_ih[c + 3];
    float biz0 = b_ih[D + c],     biz1 = b_ih[D + c + 1],     biz2 = b_ih[D + c + 2],     biz3 = b_ih[D + c + 3];
    float bin0 = b_ih[2 * D + c], bin1 = b_ih[2 * D + c + 1], bin2 = b_ih[2 * D + c + 2], bin3 = b_ih[2 * D + c + 3];
    float bhr0 = b_hh[c],         bhr1 = b_hh[c + 1],         bhr2 = b_hh[c + 2],         bhr3 = b_hh[c + 3];
    float bhz0 = b_hh[D + c],     bhz1 = b_hh[D + c + 1],     bhz2 = b_hh[D + c + 2],     bhz3 = b_hh[D + c + 3];
    float bhn0 = b_hh[2 * D + c], bhn1 = b_hh[2 * D + c + 1], bhn2 = b_hh[2 * D + c + 2], bhn3 = b_hh[2 * D + c + 3];
    float4 h = *(float4*)(g_h + (size_t)n * D + c);
    h.x = gru1(ir.x + bir0, iz.x + biz0, inn.x + bin0, hr.x + bhr0, hz.x + bhz0, hn.x + bhn0, h.x);
    h.y = gru1(ir.y + bir1, iz.y + biz1, inn.y + bin1, hr.y + bhr1, hz.y + bhz1, hn.y + bhn1, h.y);
    h.z = gru1(ir.z + bir2, iz.z + biz2, inn.z + bin2, hr.z + bhr2, hz.z + bhz2, hn.z + bhn2, h.z);
    h.w = gru1(ir.w + bir3, iz.w + biz3, inn.w + bin3, hr.w + bhr3, hz.w + bhz3, hn.w + bhn3, h.w);
    *(float4*)(g_h + (size_t)n * D + c) = h;
}

// ---------------- relu + max-pool --------------------------------------------
// pool pre-zeroed; post-ReLU values >= 0 so int-bit atomicMax is order-preserving.
__global__ void maxpool_kernel() {
    int d = threadIdx.x;
    if (d >= D) return;
    float v = 0.f;  // ReLU floor
    for (int n = blockIdx.x; n < N_NODES; n += gridDim.x)
        v = fmaxf(v, g_h[(size_t)n * D + d]);
    atomicMax((int*)&g_pool[d], __float_as_int(v));
}

// ---------------- classifier + softmax ---------------------------------------
__global__ void logits_kernel(const float* __restrict__ cls_w,
                              const float* __restrict__ cls_b,
                              float* __restrict__ out) {
    __shared__ float s0[256], s1[256];
    int t = threadIdx.x;
    float p0 = 0.f, p1 = 0.f;
    for (int d = t; d < D; d += 256) {
        float pv = g_pool[d];
        p0 += pv * cls_w[d];
        p1 += pv * cls_w[D + d];
    }
    s0[t] = p0; s1[t] = p1;
    __syncthreads();
    for (int s = 128; s > 0; s >>= 1) {
        if (t < s) { s0[t] += s0[t + s]; s1[t] += s1[t + s]; }
        __syncthreads();
    }
    if (t == 0) {
        float l0 = s0[0] + cls_b[0], l1 = s1[0] + cls_b[1];
        float mx = fmaxf(l0, l1);
        float e0 = expf(l0 - mx), e1 = expf(l1 - mx);
        float inv = 1.f / (e0 + e1);
        out[0] = e0 * inv;
        out[1] = e1 * inv;
    }
}

// ---------------- host driver -------------------------------------------------
extern "C" void kernel_launch(void* const* d_in, const int* in_sizes, int n_in,
                              void* d_out, int out_size) {
    // Map inputs by element count (robust to ordering). Ties (w_ih/w_hh,
    // b_ih/b_hh) resolved by declaration order in the reference.
    const float* x = 0; const float* W = 0;
    const float* w_ih = 0; const float* w_hh = 0;
    const float* b_ih = 0; const float* b_hh = 0;
    const float* cls_w = 0; const float* cls_b = 0;
    const void* ei = 0;
    for (int i = 0; i < n_in; i++) {
        int sz = in_sizes[i];
        const void* p = d_in[i];
        if      (sz == N_NODES * IN_DIM) x = (const float*)p;
        else if (sz == NUM_STEPS * D * D) W = (const float*)p;
        else if (sz == D3 * D) { if (!w_ih) w_ih = (const float*)p; else w_hh = (const float*)p; }
        else if (sz == D3)     { if (!b_ih) b_ih = (const float*)p; else b_hh = (const float*)p; }
        else if (sz == 2 * D)  cls_w = (const float*)p;
        else if (sz == 2)      cls_b = (const float*)p;
        else if (sz == 2 * E_EDGES) ei = p;
    }
    float* out = (float*)d_out;

    float *h, *m, *aggr, *gi, *gh, *Bih, *Bhh, *pool;
    cudaGetSymbolAddress((void**)&h, g_h);
    cudaGetSymbolAddress((void**)&m, g_m);
    cudaGetSymbolAddress((void**)&aggr, g_aggr);
    cudaGetSymbolAddress((void**)&gi, g_gi);
    cudaGetSymbolAddress((void**)&gh, g_gh);
    cudaGetSymbolAddress((void**)&Bih, g_Bih);
    cudaGetSymbolAddress((void**)&Bhh, g_Bhh);
    cudaGetSymbolAddress((void**)&pool, g_pool);

    const int TB = 256;

    // edge dtype detect + convert to int32 src/dst
    detect_ei_kernel<<<1, 32>>>((const unsigned int*)ei);
    convert_ei_kernel<<<(E_EDGES + TB - 1) / TB, TB>>>(ei);

    // h = pad(x); Bih = w_ih^T; Bhh = w_hh^T
    init_h_kernel<<<(N_NODES * D + TB - 1) / TB, TB>>>(x);
    transpose_kernel<<<(D3 * D + TB - 1) / TB, TB>>>(w_ih, Bih);
    transpose_kernel<<<(D3 * D + TB - 1) / TB, TB>>>(w_hh, Bhh);

    dim3 gridM(2, (N_NODES + 127) / 128);   // Nc=200
    dim3 gridG(5, (N_NODES + 127) / 128);   // Nc=600

    for (int step = 0; step < NUM_STEPS; step++) {
        // m = h @ W[step]
        sgemm128<<<gridM, TB>>>(h, W + (size_t)step * D * D, m, N_NODES, D, D);
        // aggr = scatter_add(m[src] -> dst)
        zero4_kernel<<<(N_NODES * 50 + TB - 1) / TB, TB>>>(aggr, N_NODES * 50);
        scatter_add_kernel<<<(E_EDGES * 50 + TB - 1) / TB, TB>>>();
        // gi = aggr @ w_ih^T ; gh = h @ w_hh^T
        sgemm128<<<gridG, TB>>>(aggr, Bih, gi, N_NODES, D3, D);
        sgemm128<<<gridG, TB>>>(h, Bhh, gh, N_NODES, D3, D);
        // h = GRU(aggr-gates, h-gates, h)
        gru_kernel<<<(N_NODES * 50 + TB - 1) / TB, TB>>>(b_ih, b_hh);
    }

    // pooled = max over nodes of relu(h); logits -> softmax
    zero4_kernel<<<1, TB>>>(pool, D / 4);
    maxpool_kernel<<<1024, TB>>>();
    logits_kernel<<<1, TB>>>(cls_w, cls_b, out);
}

// round 4
// speedup vs baseline: 1.0905x; 1.0905x over previous
#include <cuda_runtime.h>
#include <math.h>
#include <mma.h>

using namespace nvcuda;

#define N_NODES 100000
#define E_EDGES 400000
#define IN_DIM  100
#define D       200
#define D3      600
#define NUM_STEPS 4

// ---------------- scratch (static device globals; 16B-aligned for float4) ----
__device__ __align__(16) float g_h   [(size_t)N_NODES * D];
__device__ __align__(16) float g_m   [(size_t)N_NODES * D];
__device__ __align__(16) float g_aggr[(size_t)N_NODES * D];
__device__ __align__(16) float g_gi  [(size_t)N_NODES * D3];
__device__ __align__(16) float g_gh  [(size_t)N_NODES * D3];
__device__ __align__(16) float g_Bih [D * D3];
__device__ __align__(16) float g_Bhh [D * D3];
__device__ __align__(16) float g_pool[D];
__device__ int g_src[E_EDGES];
__device__ int g_dst[E_EDGES];
__device__ int g_ei_is64;

// ---------------- edge-index dtype detection + conversion --------------------
__global__ void detect_ei_kernel(const unsigned int* __restrict__ w) {
    if (threadIdx.x == 0) {
        int is64 = 1;
        for (int i = 0; i < 4096; i++)
            if (w[2 * i + 1] != 0u) { is64 = 0; break; }
        g_ei_is64 = is64;
    }
}

__global__ void convert_ei_kernel(const void* __restrict__ ei) {
    int e = blockIdx.x * blockDim.x + threadIdx.x;
    if (e >= E_EDGES) return;
    int s, d;
    if (g_ei_is64) {
        const long long* p = (const long long*)ei;
        s = (int)p[e];
        d = (int)p[E_EDGES + e];
    } else {
        const int* p = (const int*)ei;
        s = p[e];
        d = p[E_EDGES + e];
    }
    s = min(max(s, 0), N_NODES - 1);
    d = min(max(d, 0), N_NODES - 1);
    g_src[e] = s;
    g_dst[e] = d;
}

// ---------------- helpers ----------------------------------------------------
__global__ void zero4_kernel(float* __restrict__ p, int n4) {
    int i = blockIdx.x * blockDim.x + threadIdx.x;
    if (i < n4) ((float4*)p)[i] = make_float4(0.f, 0.f, 0.f, 0.f);
}

__global__ void init_h_kernel(const float* __restrict__ x) {
    int idx = blockIdx.x * blockDim.x + threadIdx.x;
    if (idx >= N_NODES * D) return;
    int n = idx / D, d = idx - n * D;
    g_h[idx] = (d < IN_DIM) ? x[n * IN_DIM + d] : 0.f;
}

// w: [D3, D] row-major  ->  o: [D, D3] row-major  (o = w^T)
__global__ void transpose_kernel(const float* __restrict__ w, float* __restrict__ o) {
    int idx = blockIdx.x * blockDim.x + threadIdx.x;
    if (idx >= D3 * D) return;
    int r = idx / D, c = idx - r * D;
    o[c * D3 + r] = w[idx];
}

// ---------------- TF32 tensor-core GEMM: C[M,Nc] = A[M,K] @ B[K,Nc] ----------
// Block tile 128x128, BK=16 (two k=8 steps). 8 warps in 4(M) x 2(N), each warp
// owns a 32x64 tile = 2x4 wmma m16n16k8 accumulators. A/B staged in padded
// SMEM; C staged through per-warp SMEM then guarded float4 global stores.
#define BM 128
#define BN 128
#define BK 16
#define A_LD 20     // 16 + 4 pad (floats); 80B row stride, 16B-aligned slots
#define B_LD 132    // 128 + 4 pad; 528B stride
#define C_LD 68     // 64 + 4 pad; 272B stride
#define SMEM_A_FLOATS (BM * A_LD)            // 2560
#define SMEM_B_FLOATS (BK * B_LD)            // 2112
#define SMEM_C_FLOATS (8 * 32 * C_LD)        // 17408
#define GEMM_SMEM_BYTES ((SMEM_A_FLOATS + SMEM_B_FLOATS + SMEM_C_FLOATS) * 4)

__global__ __launch_bounds__(256) void gemm_tf32(
    const float* __restrict__ A, const float* __restrict__ B, float* __restrict__ C,
    int M, int Nc, int K)
{
    extern __shared__ float smem[];
    float* As = smem;                       // [BM][A_LD]
    float* Bs = As + SMEM_A_FLOATS;         // [BK][B_LD]
    float* Cs = Bs + SMEM_B_FLOATS;         // 8 x [32][C_LD]

    const int tid  = threadIdx.x;
    const int wid  = tid >> 5;
    const int lane = tid & 31;
    const int wm   = wid & 3;               // warp row 0..3 (32 rows each)
    const int wn   = wid >> 2;              // warp col 0..1 (64 cols each)
    const int rowBase = blockIdx.y * BM;
    const int colBase = blockIdx.x * BN;

    wmma::fragment<wmma::accumulator, 16, 16, 8, float> c[2][4];
#pragma unroll
    for (int i = 0; i < 2; i++)
#pragma unroll
        for (int j = 0; j < 4; j++) wmma::fill_fragment(c[i][j], 0.f);

    for (int k0 = 0; k0 < K; k0 += BK) {
        // ---- stage A: 128 x 16 (512 float4, 2 per thread), zero-fill OOB ----
#pragma unroll
        for (int f = tid; f < 512; f += 256) {
            int r = f >> 2, cc = (f & 3) * 4;
            float4 v = make_float4(0.f, 0.f, 0.f, 0.f);
            int gr = rowBase + r, gc = k0 + cc;
            if (gr < M) {
                const float* src = A + (size_t)gr * K + gc;
                if (gc + 3 < K) v = *(const float4*)src;
                else {
                    if (gc + 0 < K) v.x = src[0];
                    if (gc + 1 < K) v.y = src[1];
                    if (gc + 2 < K) v.z = src[2];
                }
            }
            *(float4*)(As + r * A_LD + cc) = v;
        }
        // ---- stage B: 16 x 128 (512 float4, 2 per thread), zero-fill OOB ----
#pragma unroll
        for (int f = tid; f < 512; f += 256) {
            int r = f >> 5, cc = (f & 31) * 4;
            float4 v = make_float4(0.f, 0.f, 0.f, 0.f);
            int gr = k0 + r, gc = colBase + cc;
            if (gr < K) {
                const float* src = B + (size_t)gr * Nc + gc;
                if (gc + 3 < Nc) v = *(const float4*)src;
                else {
                    if (gc + 0 < Nc) v.x = src[0];
                    if (gc + 1 < Nc) v.y = src[1];
                    if (gc + 2 < Nc) v.z = src[2];
                }
            }
            *(float4*)(Bs + r * B_LD + cc) = v;
        }
        __syncthreads();

        // ---- compute: two k=8 steps ----
#pragma unroll
        for (int ks = 0; ks < 2; ks++) {
            const int kk = ks * 8;
            wmma::fragment<wmma::matrix_a, 16, 16, 8, wmma::precision::tf32, wmma::row_major> a0, a1;
            wmma::load_matrix_sync(a0, As + (wm * 32 + 0)  * A_LD + kk, A_LD);
            wmma::load_matrix_sync(a1, As + (wm * 32 + 16) * A_LD + kk, A_LD);
#pragma unroll
            for (int t = 0; t < a0.num_elements; t++) {
                a0.x[t] = wmma::__float_to_tf32(a0.x[t]);
                a1.x[t] = wmma::__float_to_tf32(a1.x[t]);
            }
#pragma unroll
            for (int j = 0; j < 4; j++) {
                wmma::fragment<wmma::matrix_b, 16, 16, 8, wmma::precision::tf32, wmma::row_major> b;
                wmma::load_matrix_sync(b, Bs + kk * B_LD + wn * 64 + j * 16, B_LD);
#pragma unroll
                for (int t = 0; t < b.num_elements; t++) b.x[t] = wmma::__float_to_tf32(b.x[t]);
                wmma::mma_sync(c[0][j], a0, b, c[0][j]);
                wmma::mma_sync(c[1][j], a1, b, c[1][j]);
            }
        }
        __syncthreads();
    }

    // ---- epilogue: stage C through per-warp SMEM, guarded float4 stores -----
    float* myCs = Cs + wid * (32 * C_LD);
#pragma unroll
    for (int i = 0; i < 2; i++)
#pragma unroll
        for (int j = 0; j < 4; j++)
            wmma::store_matrix_sync(myCs + i * 16 * C_LD + j * 16, c[i][j], C_LD, wmma::mem_row_major);
    __syncwarp();

#pragma unroll
    for (int f = lane; f < 512; f += 32) {   // 32 rows x 16 float4
        int r = f >> 4, cc = (f & 15) * 4;
        int gr = rowBase + wm * 32 + r;
        int gc = colBase + wn * 64 + cc;
        if (gr < M) {
            float4 v = *(float4*)(myCs + r * C_LD + cc);
            float* dst = C + (size_t)gr * Nc + gc;
            if (gc + 3 < Nc) *(float4*)dst = v;
            else {
                if (gc + 0 < Nc) dst[0] = v.x;
                if (gc + 1 < Nc) dst[1] = v.y;
                if (gc + 2 < Nc) dst[2] = v.z;
            }
        }
    }
}

// ---------------- edge scatter-add: aggr[dst] += m[src] ----------------------
__global__ void scatter_add_kernel() {
    int idx = blockIdx.x * blockDim.x + threadIdx.x;
    if (idx >= E_EDGES * 50) return;
    int e = idx / 50;
    int c = (idx - e * 50) * 4;
    int s = g_src[e];
    int d = g_dst[e];
    float4 v = *(const float4*)(g_m + (size_t)s * D + c);
    float* out = g_aggr + (size_t)d * D + c;
    atomicAdd(out + 0, v.x);
    atomicAdd(out + 1, v.y);
    atomicAdd(out + 2, v.z);
    atomicAdd(out + 3, v.w);
}

// ---------------- GRU elementwise --------------------------------------------
__device__ __forceinline__ float gru1(float ir, float iz, float inn,
                                      float hr, float hz, float hn, float h) {
    float r = 1.f / (1.f + expf(-(ir + hr)));
    float z = 1.f / (1.f + expf(-(iz + hz)));
    float n = tanhf(inn + r * hn);
    return (1.f - z) * n + z * h;
}

__global__ void gru_kernel(const float* __restrict__ b_ih, const float* __restrict__ b_hh) {
    int idx = blockIdx.x * blockDim.x + threadIdx.x;
    if (idx >= N_NODES * 50) return;
    int n = idx / 50;
    int c = (idx - n * 50) * 4;
    size_t gbase = (size_t)n * D3;
    float4 ir  = *(const float4*)(g_gi + gbase + c);
    float4 iz  = *(const float4*)(g_gi + gbase + D + c);
    float4 inn = *(const float4*)(g_gi + gbase + 2 * D + c);
    float4 hr  = *(const float4*)(g_gh + gbase + c);
    float4 hz  = *(const float4*)(g_gh + gbase + D + c);
    float4 hn  = *(const float4*)(g_gh + gbase + 2 * D + c);
    float bir0 = b_ih[c],         bir1 = b_ih[c + 1],         bir2 = b_ih[c + 2],         bir3 = b_ih[c + 3];
    float biz0 = b_ih[D + c],     biz1 = b_ih[D + c + 1],     biz2 = b_ih[D + c + 2],     biz3 = b_ih[D + c + 3];
    float bin0 = b_ih[2 * D + c], bin1 = b_ih[2 * D + c + 1], bin2 = b_ih[2 * D + c + 2], bin3 = b_ih[2 * D + c + 3];
    float bhr0 = b_hh[c],         bhr1 = b_hh[c + 1],         bhr2 = b_hh[c + 2],         bhr3 = b_hh[c + 3];
    float bhz0 = b_hh[D + c],     bhz1 = b_hh[D + c + 1],     bhz2 = b_hh[D + c + 2],     bhz3 = b_hh[D + c + 3];
    float bhn0 = b_hh[2 * D + c], bhn1 = b_hh[2 * D + c + 1], bhn2 = b_hh[2 * D + c + 2], bhn3 = b_hh[2 * D + c + 3];
    float4 h = *(float4*)(g_h + (size_t)n * D + c);
    h.x = gru1(ir.x + bir0, iz.x + biz0, inn.x + bin0, hr.x + bhr0, hz.x + bhz0, hn.x + bhn0, h.x);
    h.y = gru1(ir.y + bir1, iz.y + biz1, inn.y + bin1, hr.y + bhr1, hz.y + bhz1, hn.y + bhn1, h.y);
    h.z = gru1(ir.z + bir2, iz.z + biz2, inn.z + bin2, hr.z + bhr2, hz.z + bhz2, hn.z + bhn2, h.z);
    h.w = gru1(ir.w + bir3, iz.w + biz3, inn.w + bin3, hr.w + bhr3, hz.w + bhz3, hn.w + bhn3, h.w);
    *(float4*)(g_h + (size_t)n * D + c) = h;
}

// ---------------- relu + max-pool --------------------------------------------
__global__ void maxpool_kernel() {
    int d = threadIdx.x;
    if (d >= D) return;
    float v = 0.f;  // ReLU floor
    for (int n = blockIdx.x; n < N_NODES; n += gridDim.x)
        v = fmaxf(v, g_h[(size_t)n * D + d]);
    atomicMax((int*)&g_pool[d], __float_as_int(v));
}

// ---------------- classifier + softmax ---------------------------------------
__global__ void logits_kernel(const float* __restrict__ cls_w,
                              const float* __restrict__ cls_b,
                              float* __restrict__ out) {
    __shared__ float s0[256], s1[256];
    int t = threadIdx.x;
    float p0 = 0.f, p1 = 0.f;
    for (int d = t; d < D; d += 256) {
        float pv = g_pool[d];
        p0 += pv * cls_w[d];
        p1 += pv * cls_w[D + d];
    }
    s0[t] = p0; s1[t] = p1;
    __syncthreads();
    for (int s = 128; s > 0; s >>= 1) {
        if (t < s) { s0[t] += s0[t + s]; s1[t] += s1[t + s]; }
        __syncthreads();
    }
    if (t == 0) {
        float l0 = s0[0] + cls_b[0], l1 = s1[0] + cls_b[1];
        float mx = fmaxf(l0, l1);
        float e0 = expf(l0 - mx), e1 = expf(l1 - mx);
        float inv = 1.f / (e0 + e1);
        out[0] = e0 * inv;
        out[1] = e1 * inv;
    }
}

// ---------------- host driver -------------------------------------------------
extern "C" void kernel_launch(void* const* d_in, const int* in_sizes, int n_in,
                              void* d_out, int out_size) {
    // Map inputs by element count (ties resolved by declaration order).
    const float* x = 0; const float* W = 0;
    const float* w_ih = 0; const float* w_hh = 0;
    const float* b_ih = 0; const float* b_hh = 0;
    const float* cls_w = 0; const float* cls_b = 0;
    const void* ei = 0;
    for (int i = 0; i < n_in; i++) {
        int sz = in_sizes[i];
        const void* p = d_in[i];
        if      (sz == N_NODES * IN_DIM) x = (const float*)p;
        else if (sz == NUM_STEPS * D * D) W = (const float*)p;
        else if (sz == D3 * D) { if (!w_ih) w_ih = (const float*)p; else w_hh = (const float*)p; }
        else if (sz == D3)     { if (!b_ih) b_ih = (const float*)p; else b_hh = (const float*)p; }
        else if (sz == 2 * D)  cls_w = (const float*)p;
        else if (sz == 2)      cls_b = (const float*)p;
        else if (sz == 2 * E_EDGES) ei = p;
    }
    float* out = (float*)d_out;

    float *h, *m, *aggr, *gi, *gh, *Bih, *Bhh, *pool;
    cudaGetSymbolAddress((void**)&h, g_h);
    cudaGetSymbolAddress((void**)&m, g_m);
    cudaGetSymbolAddress((void**)&aggr, g_aggr);
    cudaGetSymbolAddress((void**)&gi, g_gi);
    cudaGetSymbolAddress((void**)&gh, g_gh);
    cudaGetSymbolAddress((void**)&Bih, g_Bih);
    cudaGetSymbolAddress((void**)&Bhh, g_Bhh);
    cudaGetSymbolAddress((void**)&pool, g_pool);

    const int TB = 256;

    cudaFuncSetAttribute(gemm_tf32, cudaFuncAttributeMaxDynamicSharedMemorySize,
                         GEMM_SMEM_BYTES);

    // edge dtype detect + convert to int32 src/dst
    detect_ei_kernel<<<1, 32>>>((const unsigned int*)ei);
    convert_ei_kernel<<<(E_EDGES + TB - 1) / TB, TB>>>(ei);

    // h = pad(x); Bih = w_ih^T; Bhh = w_hh^T
    init_h_kernel<<<(N_NODES * D + TB - 1) / TB, TB>>>(x);
    transpose_kernel<<<(D3 * D + TB - 1) / TB, TB>>>(w_ih, Bih);
    transpose_kernel<<<(D3 * D + TB - 1) / TB, TB>>>(w_hh, Bhh);

    dim3 gridM((D  + BN - 1) / BN, (N_NODES + BM - 1) / BM);   // 2 x 782
    dim3 gridG((D3 + BN - 1) / BN, (N_NODES + BM - 1) / BM);   // 5 x 782

    for (int step = 0; step < NUM_STEPS; step++) {
        // m = h @ W[step]
        gemm_tf32<<<gridM, TB, GEMM_SMEM_BYTES>>>(h, W + (size_t)step * D * D, m, N_NODES, D, D);
        // aggr = scatter_add(m[src] -> dst)
        zero4_kernel<<<(N_NODES * 50 + TB - 1) / TB, TB>>>(aggr, N_NODES * 50);
        scatter_add_kernel<<<(E_EDGES * 50 + TB - 1) / TB, TB>>>();
        // gi = aggr @ w_ih^T ; gh = h @ w_hh^T
        gemm_tf32<<<gridG, TB, GEMM_SMEM_BYTES>>>(aggr, Bih, gi, N_NODES, D3, D);
        gemm_tf32<<<gridG, TB, GEMM_SMEM_BYTES>>>(h, Bhh, gh, N_NODES, D3, D);
        // h = GRU(aggr-gates, h-gates, h)
        gru_kernel<<<(N_NODES * 50 + TB - 1) / TB, TB>>>(b_ih, b_hh);
    }

    // pooled = max over nodes of relu(h); logits -> softmax
    zero4_kernel<<<1, TB>>>(pool, D / 4);
    maxpool_kernel<<<1024, TB>>>();
    logits_kernel<<<1, TB>>>(cls_w, cls_b, out);
}